// round 14
// baseline (speedup 1.0000x reference)
#include <cuda_runtime.h>
#include <cstdint>

#define BATCH 4
#define NPTS  4096
#define FIN   64
#define FOUT  64
#define KNN   20
#define TOTAL (BATCH * NPTS)   // 16384 points

// ---------------- scratch (static device memory; no allocations) ----------------
__device__ float g_key[(size_t)TOTAL * NPTS];   // 268 MB ranking keys
__device__ float g_u[TOTAL * FOUT];             // (W1-W2)x + b
__device__ float g_v[TOTAL * FOUT];             // W2 x
__device__ float g_xs[TOTAL];                   // squared norms
__device__ int   g_idx[TOTAL * KNN];            // knn indices (local to batch)

// ---------------- kernel A: per-point transform ----------------
__global__ void transform_kernel(const float* __restrict__ x,
                                 const float* __restrict__ W,
                                 const float* __restrict__ bias) {
    __shared__ float Ws[FOUT * 2 * FIN];
    __shared__ float bs[FOUT];
    int t = threadIdx.x;
    for (int i = t; i < FOUT * 2 * FIN; i += blockDim.x) Ws[i] = W[i];
    if (t < FOUT) bs[t] = bias[t];
    __syncthreads();

    int p = blockIdx.x * blockDim.x + t;
    float xr[FIN];
    const float4* xp = (const float4*)(x + (size_t)p * FIN);
#pragma unroll
    for (int q = 0; q < FIN / 4; q++) {
        float4 v4 = xp[q];
        xr[4*q+0] = v4.x; xr[4*q+1] = v4.y; xr[4*q+2] = v4.z; xr[4*q+3] = v4.w;
    }
    float s = 0.f;
#pragma unroll
    for (int c = 0; c < FIN; c++) s += xr[c] * xr[c];
    g_xs[p] = s;

    for (int o = 0; o < FOUT; o++) {
        float a1 = 0.f, a2 = 0.f;
        const float* wrow = &Ws[o * 2 * FIN];
#pragma unroll
        for (int c = 0; c < FIN; c++) {
            a1 += xr[c] * wrow[c];
            a2 += xr[c] * wrow[FIN + c];
        }
        g_u[p * FOUT + o] = a1 - a2 + bs[o];
        g_v[p * FOUT + o] = a2;
    }
}

// ---------------- kernel B: Gram + keys via split-TF32 tensor cores ----------------
// key[i][j] = xs[j] - 2*dot(x_i,x_j). Full grid (no symmetry trick) so every
// store is coalesced. dot via 3-term truncation split: exact hi = x&~0x1FFF,
// lo = x - hi (exact); dot = hi*hi + lo*hi + hi*lo (err ~2^-22 rel).
#define DSTR 68
#define DIST_SMEM ((2 * 128 * DSTR + 128) * 4)   // 70,144 bytes

__device__ __forceinline__ void mma_tf32(float* c, const unsigned* a, const unsigned* b) {
    asm volatile(
        "mma.sync.aligned.m16n8k8.row.col.f32.tf32.tf32.f32 "
        "{%0,%1,%2,%3}, {%4,%5,%6,%7}, {%8,%9}, {%0,%1,%2,%3};"
        : "+f"(c[0]), "+f"(c[1]), "+f"(c[2]), "+f"(c[3])
        : "r"(a[0]), "r"(a[1]), "r"(a[2]), "r"(a[3]), "r"(b[0]), "r"(b[1]));
}

__global__ __launch_bounds__(256) void dist_kernel(const float* __restrict__ x) {
    extern __shared__ float sm[];
    float* As  = sm;                    // [128][DSTR] rows tile
    float* Bs  = sm + 128 * DSTR;       // [128][DSTR] cols tile
    float* xsS = sm + 2 * 128 * DSTR;   // [128] xs of cols

    int b  = blockIdx.z;
    int row0 = blockIdx.y * 128, col0 = blockIdx.x * 128;
    int t = threadIdx.x, lane = t & 31, w = t >> 5;

    const float* Xb = x + (size_t)b * NPTS * FIN;
    for (int q = t; q < 128 * 16; q += 256) {
        int r = q >> 4, c4 = (q & 15) * 4;
        *(float4*)&As[r * DSTR + c4] = *(const float4*)(Xb + (size_t)(row0 + r) * FIN + c4);
        *(float4*)&Bs[r * DSTR + c4] = *(const float4*)(Xb + (size_t)(col0 + r) * FIN + c4);
    }
    if (t < 128) xsS[t] = g_xs[b * NPTS + col0 + t];
    __syncthreads();

    // warp w -> rows [w*16, w*16+16); 16 n-tiles of 8 cols
    float acc[16][4];
#pragma unroll
    for (int nt = 0; nt < 16; nt++)
#pragma unroll
        for (int e = 0; e < 4; e++) acc[nt][e] = 0.f;

    int g  = lane >> 2;    // groupID
    int tg = lane & 3;     // threadID_in_group
    const float* Ab = As + (w * 16 + g) * DSTR + tg;
    const float* Bb = Bs + g * DSTR + tg;

#pragma unroll
    for (int k0 = 0; k0 < FIN; k0 += 8) {
        // A fragment (m16n8k8 row-major): a0=(g,tg) a1=(g+8,tg) a2=(g,tg+4) a3=(g+8,tg+4)
        float af[4] = { Ab[k0], Ab[8 * DSTR + k0], Ab[k0 + 4], Ab[8 * DSTR + k0 + 4] };
        unsigned ah[4], al[4];
#pragma unroll
        for (int e = 0; e < 4; e++) {
            ah[e] = __float_as_uint(af[e]) & 0xFFFFE000u;           // exact hi
            al[e] = __float_as_uint(af[e] - __uint_as_float(ah[e])); // exact lo
        }
#pragma unroll
        for (int nt = 0; nt < 16; nt++) {
            // B fragment (col-major 8x8): b0 = B[k=tg][n=g] = Bs[n][k]; b1 = k+4
            float b0f = Bb[nt * 8 * DSTR + k0];
            float b1f = Bb[nt * 8 * DSTR + k0 + 4];
            unsigned bh[2], bl[2];
            bh[0] = __float_as_uint(b0f) & 0xFFFFE000u;
            bh[1] = __float_as_uint(b1f) & 0xFFFFE000u;
            bl[0] = __float_as_uint(b0f - __uint_as_float(bh[0]));
            bl[1] = __float_as_uint(b1f - __uint_as_float(bh[1]));
            mma_tf32(acc[nt], ah, bh);
            mma_tf32(acc[nt], al, bh);
            mma_tf32(acc[nt], ah, bl);
        }
    }

    // epilogue: C frag c0=(g, 2tg) c1=(g, 2tg+1) c2=(g+8, 2tg) c3=(g+8, 2tg+1)
    size_t rowA = (size_t)(b * NPTS + row0 + w * 16 + g);
    size_t rowB = rowA + 8;
#pragma unroll
    for (int nt = 0; nt < 16; nt++) {
        int jc = nt * 8 + tg * 2;
        float xs0 = xsS[jc], xs1 = xsS[jc + 1];
        int j0 = col0 + jc;
        __stcs((float2*)&g_key[rowA * NPTS + j0],
               make_float2(xs0 - 2.f * acc[nt][0], xs1 - 2.f * acc[nt][1]));
        __stcs((float2*)&g_key[rowB * NPTS + j0],
               make_float2(xs0 - 2.f * acc[nt][2], xs1 - 2.f * acc[nt][3]));
    }
}

// ---------------- kernel C: 2-pass radix + survivor compaction (unchanged) ----------------
__global__ __launch_bounds__(256) void select_kernel() {
    int row = blockIdx.x;
    int iLocal = row & (NPTS - 1);
    const float4* keys = (const float4*)(g_key + (size_t)row * NPTS);
    int t = threadIdx.x;

    unsigned v[16];
#pragma unroll
    for (int i2 = 0; i2 < 4; i2++) {
        int f4 = t + i2 * 256;
        float4 kv = __ldcs(&keys[f4]);
        float vv[4] = {kv.x, kv.y, kv.z, kv.w};
        int j0 = f4 * 4;
#pragma unroll
        for (int e = 0; e < 4; e++) {
            unsigned u = __float_as_uint(vv[e]);
            u = (u & 0x80000000u) ? ~u : (u | 0x80000000u);
            v[i2 * 4 + e] = (j0 + e == iLocal) ? 0xFFFFFFFFu : u;
        }
    }

    __shared__ int hist[256];
    __shared__ int sD, sCb, sNeed;
    __shared__ int cnt1, cntT;
    __shared__ unsigned tieb[256];

    unsigned prefix = 0, pmask = 0;
    if (t == 0) sNeed = KNN;

    for (int pass = 0; pass < 2; pass++) {
        int shift = 24 - 8 * pass;
        hist[t] = 0;
        __syncthreads();
#pragma unroll
        for (int q = 0; q < 16; q++) {
            bool ok = (v[q] & pmask) == prefix;
            unsigned act = __ballot_sync(0xffffffffu, ok);
            if (ok) {
                unsigned d = (v[q] >> shift) & 255u;
                unsigned m = __match_any_sync(act, d);
                if ((t & 31) == (__ffs(m) - 1))
                    atomicAdd(&hist[d], __popc(m));
            }
        }
        __syncthreads();
        if (t < 32) {
            int s[8], tot = 0, base = t * 8;
#pragma unroll
            for (int q2 = 0; q2 < 8; q2++) { s[q2] = hist[base + q2]; tot += s[q2]; }
            int inc = tot;
#pragma unroll
            for (int off = 1; off < 32; off <<= 1) {
                int o = __shfl_up_sync(0xffffffffu, inc, off);
                if (t >= off) inc += o;
            }
            int ex = inc - tot;
            int nd = sNeed;
            if (ex < nd && nd <= inc) {
                int run = ex;
#pragma unroll
                for (int q2 = 0; q2 < 8; q2++) {
                    if (nd <= run + s[q2]) { sD = base + q2; sCb = run; break; }
                    run += s[q2];
                }
            }
        }
        __syncthreads();
        prefix |= ((unsigned)sD) << shift;
        pmask  |= 0xFFu << shift;
        if (t == 0) sNeed -= sCb;
    }

    if (t == 0) { cnt1 = 0; cntT = 0; }
    __syncthreads();
    unsigned thetaHi = prefix >> 16;
    int* outp = g_idx + row * KNN;
#pragma unroll
    for (int q = 0; q < 16; q++) {
        int j = (t + (q >> 2) * 256) * 4 + (q & 3);
        unsigned hi = v[q] >> 16;
        if (hi < thetaHi)       { int s2 = atomicAdd(&cnt1, 1); outp[s2] = j; }
        else if (hi == thetaHi) {
            int s2 = atomicAdd(&cntT, 1);
            if (s2 < 256) tieb[s2] = ((v[q] & 0xFFFFu) << 12) | (unsigned)j;
        }
    }
    __syncthreads();
    int nTie  = cntT;
    int needF = sNeed;

    if (nTie <= 256) {
        if (t < 32) {
            unsigned c[8];
#pragma unroll
            for (int i = 0; i < 8; i++) {
                int ix = t + i * 32;
                c[i] = (ix < nTie) ? tieb[ix] : 0xFFFFFFFFu;
            }
            int c1 = cnt1;
            for (int s2 = 0; s2 < needF; s2++) {
                unsigned m = 0xFFFFFFFFu;
#pragma unroll
                for (int i = 0; i < 8; i++) m = (c[i] < m) ? c[i] : m;
                unsigned r = m;
#pragma unroll
                for (int off = 16; off; off >>= 1) {
                    unsigned o = __shfl_xor_sync(0xffffffffu, r, off);
                    r = (o < r) ? o : r;
                }
                if (t == 0) outp[c1 + s2] = (int)(r & 0xFFFu);
#pragma unroll
                for (int i = 0; i < 8; i++) if (c[i] == r) c[i] = 0xFFFFFFFFu;
            }
        }
    } else {
        for (int pass = 2; pass < 4; pass++) {
            int shift = 24 - 8 * pass;
            hist[t] = 0;
            __syncthreads();
#pragma unroll
            for (int q = 0; q < 16; q++) {
                bool ok = (v[q] & pmask) == prefix;
                unsigned act = __ballot_sync(0xffffffffu, ok);
                if (ok) {
                    unsigned d = (v[q] >> shift) & 255u;
                    unsigned m = __match_any_sync(act, d);
                    if ((t & 31) == (__ffs(m) - 1))
                        atomicAdd(&hist[d], __popc(m));
                }
            }
            __syncthreads();
            if (t < 32) {
                int s[8], tot = 0, base = t * 8;
#pragma unroll
                for (int q2 = 0; q2 < 8; q2++) { s[q2] = hist[base + q2]; tot += s[q2]; }
                int inc = tot;
#pragma unroll
                for (int off = 1; off < 32; off <<= 1) {
                    int o = __shfl_up_sync(0xffffffffu, inc, off);
                    if (t >= off) inc += o;
                }
                int ex = inc - tot;
                int nd = sNeed;
                if (ex < nd && nd <= inc) {
                    int run = ex;
#pragma unroll
                    for (int q2 = 0; q2 < 8; q2++) {
                        if (nd <= run + s[q2]) { sD = base + q2; sCb = run; break; }
                        run += s[q2];
                    }
                }
            }
            __syncthreads();
            prefix |= ((unsigned)sD) << shift;
            pmask  |= 0xFFu << shift;
            if (t == 0) sNeed -= sCb;
        }
        if (t == 0) { cnt1 = 0; cntT = 0; }
        __syncthreads();
        unsigned theta = prefix;
#pragma unroll
        for (int q = 0; q < 16; q++) {
            int j = (t + (q >> 2) * 256) * 4 + (q & 3);
            if (v[q] < theta)       { int s2 = atomicAdd(&cnt1, 1); outp[s2] = j; }
            else if (v[q] == theta) { int s2 = atomicAdd(&cntT, 1); if (s2 < 256) tieb[s2] = (unsigned)j; }
        }
        __syncthreads();
        if (t == 0) {
            int nt2 = cntT < 256 ? cntT : 256;
            int nf = sNeed, c1 = cnt1;
            for (int s2 = 0; s2 < nf; s2++) {
                unsigned bi = 0, bv2 = 0xFFFFFFFFu;
                for (int q = 0; q < nt2; q++) if (tieb[q] < bv2) { bv2 = tieb[q]; bi = q; }
                tieb[bi] = 0xFFFFFFFFu;
                outp[c1 + s2] = (int)bv2;
            }
        }
    }
}

// ---------------- kernel D: gather-max epilogue ----------------
__global__ void gather_kernel(float* __restrict__ out) {
    int gid = blockIdx.x * blockDim.x + threadIdx.x;
    int p = gid >> 6;
    int o = gid & 63;
    int bbase = p & ~(NPTS - 1);
    const int* ip = g_idx + p * KNN;
    float m = -3.402823466e38f;
#pragma unroll
    for (int q = 0; q < KNN; q++) {
        int j = ip[q];
        m = fmaxf(m, g_v[(size_t)(bbase + j) * FOUT + o]);
    }
    out[gid] = g_u[gid] + m;
}

// ---------------- launch: simple single-stream sequence ----------------
extern "C" void kernel_launch(void* const* d_in, const int* in_sizes, int n_in,
                              void* d_out, int out_size) {
    const float* x    = (const float*)d_in[0];
    const float* W    = (const float*)d_in[1];
    const float* bias = (const float*)d_in[2];
    float* out = (float*)d_out;

    static bool s_init = false;
    if (!s_init) {
        s_init = true;
        cudaFuncSetAttribute(dist_kernel,
                             cudaFuncAttributeMaxDynamicSharedMemorySize, DIST_SMEM);
    }

    transform_kernel<<<TOTAL / 128, 128>>>(x, W, bias);
    dist_kernel<<<dim3(32, 32, BATCH), 256, DIST_SMEM>>>(x);
    select_kernel<<<TOTAL, 256>>>();
    gather_kernel<<<(TOTAL * FOUT) / 256, 256>>>(out);
}